// round 7
// baseline (speedup 1.0000x reference)
#include <cuda_runtime.h>
#include <math.h>

typedef unsigned long long ull;

// ---------------- problem constants ----------------
#define NB   16
#define HF   128
#define WF   128
#define CF   64
#define CH   704
#define PP   23
#define NPIX (PP*PP)      // 529
#define NROI 176
#define C1N  441          // 21*21
#define C1TOT (NB*64*C1N)

// ---------------- scratch (device globals) ----------------
__device__ float g_stem[(size_t)NB*64*256*256];     // 268 MB fp32 pre-BN
__device__ float g_f  [(size_t)NB*CF*HF*WF];
__device__ float g_xt1[(size_t)NB*CF*HF*WF];
__device__ float g_xt2[(size_t)NB*CF*HF*WF];
__device__ float g_h  [(size_t)NB*CH*NPIX];
__device__ float g_c1p[(size_t)4*C1TOT];
__device__ float g_c1 [(size_t)C1TOT];
__device__ float g_pool[(size_t)NB*64*10*10];
__device__ float g_c2 [(size_t)NB*32*8*8];
__device__ float g_spart_s[64*2048];
__device__ float g_spart_q[64*2048];
__device__ float g_stats_b[64*16*2];
__device__ float g_bn_stem[64*2];
__device__ float g_bn_c1[64*2];

// ---------------- packed f32x2 helpers ----------------
__device__ __forceinline__ ull pack2(float lo, float hi) {
    ull r; asm("mov.b64 %0, {%1, %2};" : "=l"(r) : "f"(lo), "f"(hi)); return r;
}
__device__ __forceinline__ void unpack2(float& lo, float& hi, ull v) {
    asm("mov.b64 {%0, %1}, %2;" : "=f"(lo), "=f"(hi) : "l"(v));
}
__device__ __forceinline__ void ffma2(ull& acc, ull a, ull b) {
    asm("fma.rn.f32x2 %0, %1, %2, %0;" : "+l"(acc) : "l"(a), "l"(b));
}

// ==================================================================
// Kernel 1: stem conv 7x7 s2 p3, NHWC (16,512,512,3) -> fp32 (16,64,256,256)
// block (16,8): thread = x-pair (2tx,2tx+1) x rows {ty, ty+8} x 8 oc.
// Parity-deinterleaved smem input -> conflict-free LDS.64 input pairs.
// Weights pre-duplicated (w,w) -> broadcast LDS.64. f32x2 FFMA throughout.
// Fused BN partial stats from exact fp32 accumulators.
// ==================================================================
__global__ __launch_bounds__(128) void k_stem(const float* __restrict__ x,
                                              const float* __restrict__ w) {
    __shared__ float s_pe[2*3996];    // even / odd column arrays: [par][c][37 rows][36]
    __shared__ ull   s_wd[1176];      // 147 k-positions x 8 oc, (w,w) packed
    __shared__ float s_sum[32], s_sq[32];

    const int tx = threadIdx.x;       // 0..15  -> x-pair
    const int ty = threadIdx.y;       // 0..7   -> rows ty, ty+8
    const int tid = ty*16 + tx;
    const int lane = tid & 31, wid = tid >> 5;
    const int bx = blockIdx.x, by = blockIdx.y, b = blockIdx.z;
    const int blockflat = (b*16 + by)*8 + bx;         // 0..2047
    const int iy0 = by*32 - 3;
    const int ix0 = bx*64 - 3;

    // input patch (69 cols, 37 rows, 3 ch), parity-split store
    for (int i = tid; i < 3*37*69; i += 128) {
        int py = i / 207;
        int rem = i - py*207;
        int px = rem / 3;
        int c  = rem - px*3;
        int ih = iy0 + py, iw = ix0 + px;
        float v = 0.f;
        if (ih >= 0 && ih < 512 && iw >= 0 && iw < 512)
            v = x[((size_t)(b*512 + ih)*512 + iw)*3 + c];
        s_pe[(px & 1)*3996 + (c*37 + py)*36 + (px >> 1)] = v;
    }

    for (int ocb = 0; ocb < 8; ocb++) {
        __syncthreads();   // protects s_wd reuse + prior round's s_sum reads
        for (int i = tid; i < 1176; i += 128) {
            float wv = w[(ocb*8 + (i & 7))*147 + (i >> 3)];
            s_wd[i] = pack2(wv, wv);
        }
        __syncthreads();

        ull acc[2][8];
        #pragma unroll
        for (int r = 0; r < 2; r++)
            #pragma unroll
            for (int o = 0; o < 8; o++) acc[r][o] = 0ull;

        #pragma unroll
        for (int c = 0; c < 3; c++) {
            #pragma unroll
            for (int ky = 0; ky < 7; ky++) {
                const int rA = (c*37 + 2*ty + ky)*36;   // row for output row ty
                const int rB = rA + 576;                // +16 input rows (output +8)
                const ull* wrow = s_wd + (c*49 + ky*7)*8;
                #pragma unroll
                for (int kx = 0; kx < 7; kx++) {
                    const float* base = s_pe + (kx & 1)*3996;
                    const int j = 2*tx + (kx >> 1);
                    ull iv0, iv1;
                    if ((((kx >> 1)) & 1) == 0) {       // j even -> aligned LDS.64
                        iv0 = *reinterpret_cast<const ull*>(base + rA + j);
                        iv1 = *reinterpret_cast<const ull*>(base + rB + j);
                    } else {                            // misaligned: 2 scalar + pack
                        iv0 = pack2(base[rA + j], base[rA + j + 1]);
                        iv1 = pack2(base[rB + j], base[rB + j + 1]);
                    }
                    #pragma unroll
                    for (int o = 0; o < 8; o++) {
                        ull wv = wrow[kx*8 + o];
                        ffma2(acc[0][o], iv0, wv);
                        ffma2(acc[1][o], iv1, wv);
                    }
                }
            }
        }

        // epilogue: float2 stores + fused per-oc stats
        #pragma unroll
        for (int o = 0; o < 8; o++) {
            int oc = ocb*8 + o;
            float l0, h0, l1, h1;
            unpack2(l0, h0, acc[0][o]);
            unpack2(l1, h1, acc[1][o]);
            size_t addr = ((size_t)(b*64 + oc)*256 + by*16 + ty)*256 + bx*32 + 2*tx;
            float2 v0; v0.x = l0; v0.y = h0;
            float2 v1; v1.x = l1; v1.y = h1;
            *reinterpret_cast<float2*>(g_stem + addr)            = v0;
            *reinterpret_cast<float2*>(g_stem + addr + 8*256)    = v1;
            float s = l0 + h0 + l1 + h1;
            float q = l0*l0 + h0*h0 + l1*l1 + h1*h1;
            #pragma unroll
            for (int off = 16; off; off >>= 1) {
                s += __shfl_xor_sync(0xffffffffu, s, off);
                q += __shfl_xor_sync(0xffffffffu, q, off);
            }
            if (lane == 0) { s_sum[wid*8 + o] = s; s_sq[wid*8 + o] = q; }
        }
        __syncthreads();
        if (tid < 16) {
            int o = tid >> 1;
            if ((tid & 1) == 0) {
                float S = s_sum[o] + s_sum[8+o] + s_sum[16+o] + s_sum[24+o];
                g_spart_s[(ocb*8 + o)*2048 + blockflat] = S;
            } else {
                float Q = s_sq[o] + s_sq[8+o] + s_sq[16+o] + s_sq[24+o];
                g_spart_q[(ocb*8 + o)*2048 + blockflat] = Q;
            }
        }
    }
}

// ==================================================================
// Kernel 2: combine stem stats -> BN scale/bias (deterministic)
// ==================================================================
__global__ void k_stem_bn_fin(const float* __restrict__ g,
                              const float* __restrict__ bta) {
    __shared__ float ss[256], sq[256];
    int oc = blockIdx.x, t = threadIdx.x;
    float S = 0.f, Q = 0.f;
    #pragma unroll
    for (int j = 0; j < 8; j++) {
        int idx = oc*2048 + t*8 + j;
        S += g_spart_s[idx];
        Q += g_spart_q[idx];
    }
    ss[t] = S; sq[t] = Q;
    __syncthreads();
    for (int st = 128; st > 0; st >>= 1) {
        if (t < st) { ss[t] += ss[t+st]; sq[t] += sq[t+st]; }
        __syncthreads();
    }
    if (t == 0) {
        const float invN = 1.0f/(16.0f*65536.0f);
        float m  = ss[0]*invN;
        float v  = sq[0]*invN - m*m;
        float sc = g[oc] * rsqrtf(v + 1e-5f);
        g_bn_stem[oc*2 + 0] = sc;
        g_bn_stem[oc*2 + 1] = bta[oc] - m*sc;
    }
}

// ==================================================================
// Kernel 3: BN + ReLU + maxpool 3x3 s2 p1, vectorized (2 outputs/thread)
// ==================================================================
__global__ void k_bnpool3() {
    int idx = blockIdx.x*256 + threadIdx.x;
    if (idx >= NB*CF*HF*64) return;
    int xo2 = idx & 63;               // output x-pair (2*xo2, 2*xo2+1)
    int yo  = (idx >> 6) & 127;
    int cb  = idx >> 13;              // b*64 + c
    int c   = cb & 63;
    float sc = g_bn_stem[c*2], bi = g_bn_stem[c*2 + 1];
    const float* p = g_stem + (size_t)cb*65536;
    float m0 = -3.402823466e+38f, m1 = m0;
    #pragma unroll
    for (int ky = 0; ky < 3; ky++) {
        int iy = 2*yo - 1 + ky;
        if (iy < 0 || iy > 255) continue;
        const float* row = p + iy*256;
        float4 qv = *reinterpret_cast<const float4*>(row + 4*xo2);
        float a0 = sc*qv.x + bi, a1 = sc*qv.y + bi;
        float a2 = sc*qv.z + bi, a3 = sc*qv.w + bi;
        if (xo2 > 0) {
            float lf = sc*row[4*xo2 - 1] + bi;
            m0 = fmaxf(m0, lf);
        }
        m0 = fmaxf(m0, fmaxf(a0, a1));
        m1 = fmaxf(m1, fmaxf(a1, fmaxf(a2, a3)));
    }
    float2 outv;
    outv.x = fmaxf(m0, 0.f);
    outv.y = fmaxf(m1, 0.f);
    *reinterpret_cast<float2*>(g_f + (size_t)cb*16384 + yo*128 + 2*xo2) = outv;
}

// ==================================================================
// Kernel 4: grid_sample +/-5 deg, geometry hoisted; block (128,2)
// ==================================================================
__global__ __launch_bounds__(256) void k_gsample() {
    const int xo = threadIdx.x, yo = blockIdx.x;
    const int b = blockIdx.y, which = blockIdx.z;
    const int chalf = threadIdx.y;
    const float C5 = 0.99619469809174553f;
    const float S5 = 0.08715574274765817f;
    float gx = (float)(2*xo + 1) * (1.0f/128.0f) - 1.0f;
    float gy = (float)(2*yo + 1) * (1.0f/128.0f) - 1.0f;
    float g0, g1;
    if (which == 0) { g0 =  C5*gx + S5*gy; g1 = -S5*gx + C5*gy; }
    else            { g0 =  C5*gx - S5*gy; g1 =  S5*gx + C5*gy; }
    float ixf = ((g0 + 1.f)*128.f - 1.f)*0.5f;
    float iyf = ((g1 + 1.f)*128.f - 1.f)*0.5f;
    float x0f = floorf(ixf), y0f = floorf(iyf);
    int x0i = (int)x0f, y0i = (int)y0f;
    float lx = ixf - x0f, ly = iyf - y0f;
    float hx = 1.f - lx,  hy = 1.f - ly;
    bool vx0 = (x0i >= 0) && (x0i < 128);
    bool vx1 = (x0i + 1 >= 0) && (x0i + 1 < 128);
    bool vy0 = (y0i >= 0) && (y0i < 128);
    bool vy1 = (y0i + 1 >= 0) && (y0i + 1 < 128);
    int cx0 = min(max(x0i, 0), 127), cx1 = min(max(x0i + 1, 0), 127);
    int cy0 = min(max(y0i, 0), 127), cy1 = min(max(y0i + 1, 0), 127);
    int o00 = cy0*128 + cx0, o01 = cy0*128 + cx1;
    int o10 = cy1*128 + cx0, o11 = cy1*128 + cx1;
    float w00 = (vx0 && vy0) ? hx*hy : 0.f;
    float w01 = (vx1 && vy0) ? lx*hy : 0.f;
    float w10 = (vx0 && vy1) ? hx*ly : 0.f;
    float w11 = (vx1 && vy1) ? lx*ly : 0.f;

    const float* base = g_f + ((size_t)b*64 + chalf*32)*16384;
    float* dst = (which ? g_xt2 : g_xt1)
               + ((size_t)b*64 + chalf*32)*16384 + yo*128 + xo;
    #pragma unroll 8
    for (int c = 0; c < 32; c++) {
        const float* pl = base + c*16384;
        float v = __ldg(pl + o00)*w00 + __ldg(pl + o01)*w01
                + __ldg(pl + o10)*w10 + __ldg(pl + o11)*w11;
        dst[c*16384] = v;
    }
}

// ==================================================================
// Kernel 5: ROI align (176 rois) -> concat buffer g_h
// ==================================================================
__global__ void k_roialign(const float* __restrict__ box) {
    int idx = blockIdx.x*256 + threadIdx.x;
    if (idx >= NROI*64*NPIX) return;
    int p = idx % NPIX;
    int t = idx / NPIX;
    int c = t & 63;
    int r = t >> 6;

    const float* src; int bb, k, och;
    if (r < 112) { k = r >> 4; bb = r & 15; src = g_f; och = k*64 + c; }
    else {
        int u = r - 112; int grp = u >> 4; bb = u & 15; k = grp & 1;
        src = (grp < 2) ? g_xt1 : g_xt2;
        och = 448 + grp*64 + c;
    }
    const float* bp = box + bb*28 + k*4;
    float x1 = bp[0]*0.25f, y1v = bp[1]*0.25f, x2 = bp[2]*0.25f, y2 = bp[3]*0.25f;
    float bw = fmaxf(x2 - x1, 1.0f) * (1.0f/23.0f);
    float bh = fmaxf(y2 - y1v, 1.0f) * (1.0f/23.0f);
    int py = p / 23, px = p - py*23;
    const float* plane = src + ((size_t)bb*64 + c)*16384;

    float acc = 0.f;
    #pragma unroll
    for (int dy = 0; dy < 2; dy++) {
        float posy = (float)py + 0.25f + 0.5f*(float)dy;
        float yv = y1v + posy*bh;
        bool ey = (yv < -1.0f) || (yv > 128.0f);
        float yc  = fminf(fmaxf(yv, 0.f), 127.f);
        float y0f = floorf(yc);
        int y0 = (int)y0f; int y1i = min(y0 + 1, 127);
        float ly = yc - y0f, hy = 1.f - ly;
        #pragma unroll
        for (int dx = 0; dx < 2; dx++) {
            float posx = (float)px + 0.25f + 0.5f*(float)dx;
            float xv = x1 + posx*bw;
            bool ex = (xv < -1.0f) || (xv > 128.0f);
            float xc  = fminf(fmaxf(xv, 0.f), 127.f);
            float x0f = floorf(xc);
            int x0 = (int)x0f; int x1i = min(x0 + 1, 127);
            float lx = xc - x0f, hx = 1.f - lx;
            float v = plane[y0*128 + x0 ]*hy*hx + plane[y0*128 + x1i ]*hy*lx
                    + plane[y1i*128 + x0]*ly*hx + plane[y1i*128 + x1i]*ly*lx;
            if (ey || ex) v = 0.f;
            acc += v;
        }
    }
    g_h[((size_t)bb*CH + och)*NPIX + p] = acc * 0.25f;
}

// ==================================================================
// Kernel 6: conv1 704->64 3x3 valid, K-split x4, f32x2 FFMA, oc pairs
// ==================================================================
__global__ __launch_bounds__(128) void k_conv1(const float* __restrict__ w) {
    __shared__ float s_in[16*529];
    __shared__ ull   s_w2u[576];
    float* s_w2 = (float*)s_w2u;
    const int b = blockIdx.x, ocb = blockIdx.y, ks = blockIdx.z;
    const int tid = threadIdx.x;

    int py[4], px[4]; bool val[4];
    #pragma unroll
    for (int j = 0; j < 4; j++) {
        int p = tid + 128*j;
        val[j] = (p < C1N);
        int pc = val[j] ? p : 0;
        py[j] = pc / 21; px[j] = pc - py[j]*21;
    }

    ull acc2[4][4];
    #pragma unroll
    for (int j = 0; j < 4; j++)
        #pragma unroll
        for (int op = 0; op < 4; op++) acc2[j][op] = 0ull;

    for (int icb = ks*11; icb < ks*11 + 11; icb++) {
        __syncthreads();
        for (int i = tid; i < 16*529; i += 128) {
            int ci = i / 529, pp = i - ci*529;
            s_in[i] = g_h[((size_t)b*CH + icb*16 + ci)*NPIX + pp];
        }
        for (int i = tid; i < 1152; i += 128)
            s_w2[i] = w[(size_t)(ocb*8 + (i & 7))*6336 + icb*144 + (i >> 3)];
        __syncthreads();

        for (int ci = 0; ci < 16; ci++) {
            const float* ip = s_in + ci*529;
            const ull*   wp = &s_w2u[ci*9*4];
            #pragma unroll
            for (int ky = 0; ky < 3; ky++) {
                #pragma unroll
                for (int kx = 0; kx < 3; kx++) {
                    ull iv[4];
                    #pragma unroll
                    for (int j = 0; j < 4; j++) {
                        float t = ip[(py[j] + ky)*23 + px[j] + kx];
                        iv[j] = pack2(t, t);
                    }
                    #pragma unroll
                    for (int op = 0; op < 4; op++) {
                        ull wv = wp[(ky*3 + kx)*4 + op];
                        #pragma unroll
                        for (int j = 0; j < 4; j++) ffma2(acc2[j][op], iv[j], wv);
                    }
                }
            }
        }
    }
    #pragma unroll
    for (int op = 0; op < 4; op++) {
        #pragma unroll
        for (int j = 0; j < 4; j++) {
            float lo, hi; unpack2(lo, hi, acc2[j][op]);
            if (val[j]) {
                int oc0 = ocb*8 + 2*op;
                float* dst = g_c1p + (size_t)ks*C1TOT + ((size_t)b*64)*C1N + tid + 128*j;
                dst[(size_t)oc0*C1N]       = lo;
                dst[(size_t)(oc0 + 1)*C1N] = hi;
            }
        }
    }
}

__global__ void k_c1comb(const float* __restrict__ bias) {
    int idx = blockIdx.x*256 + threadIdx.x;
    if (idx >= C1TOT) return;
    int oc = (idx / C1N) & 63;
    float v = g_c1p[idx] + g_c1p[C1TOT + idx] + g_c1p[2*C1TOT + idx]
            + g_c1p[3*C1TOT + idx] + bias[oc];
    g_c1[idx] = v;
}

// ==================================================================
// conv1 BN stats
// ==================================================================
__global__ void k_stats(const float* __restrict__ src, float* __restrict__ partial,
                        int planeN) {
    int b = blockIdx.x, oc = blockIdx.y;
    const float* p = src + ((size_t)b*64 + oc)*(size_t)planeN;
    float s = 0.f, q = 0.f;
    for (int i = threadIdx.x; i < planeN; i += blockDim.x) {
        float v = p[i]; s += v; q += v*v;
    }
    __shared__ float ss[256], sq[256];
    ss[threadIdx.x] = s; sq[threadIdx.x] = q;
    __syncthreads();
    for (int st = 128; st > 0; st >>= 1) {
        if (threadIdx.x < st) {
            ss[threadIdx.x] += ss[threadIdx.x + st];
            sq[threadIdx.x] += sq[threadIdx.x + st];
        }
        __syncthreads();
    }
    if (threadIdx.x == 0) {
        partial[(oc*16 + b)*2 + 0] = ss[0];
        partial[(oc*16 + b)*2 + 1] = sq[0];
    }
}

__global__ void k_stats_fin(const float* __restrict__ partial,
                            const float* __restrict__ g, const float* __restrict__ bta,
                            float* __restrict__ bn, float invN) {
    int oc = threadIdx.x;
    float s = 0.f, q = 0.f;
    for (int b = 0; b < 16; b++) {
        s += partial[(oc*16 + b)*2 + 0];
        q += partial[(oc*16 + b)*2 + 1];
    }
    float m  = s*invN;
    float v  = q*invN - m*m;
    float sc = g[oc] * rsqrtf(v + 1e-5f);
    bn[oc*2 + 0] = sc;
    bn[oc*2 + 1] = bta[oc] - m*sc;
}

// ==================================================================
// Kernel 7: BN + ReLU + maxpool 2x2 s2
// ==================================================================
__global__ void k_bnpool2() {
    int idx = blockIdx.x*256 + threadIdx.x;
    if (idx >= NB*64*100) return;
    int xo = idx % 10;
    int yo = (idx / 10) % 10;
    int cb = idx / 100;
    int c  = cb & 63;
    float sc = g_bn_c1[c*2], bi = g_bn_c1[c*2 + 1];
    const float* p = g_c1 + (size_t)cb*C1N;
    float m = -3.402823466e+38f;
    #pragma unroll
    for (int dy = 0; dy < 2; dy++)
        #pragma unroll
        for (int dx = 0; dx < 2; dx++) {
            float v = sc*p[(2*yo + dy)*21 + 2*xo + dx] + bi;
            m = fmaxf(m, v);
        }
    g_pool[idx] = fmaxf(m, 0.f);
}

// ==================================================================
// Kernel 8: conv2 64->32 3x3 + ReLU, smem-staged; block per image
// ==================================================================
__global__ __launch_bounds__(256) void k_conv2(const float* __restrict__ w,
                                               const float* __restrict__ bias) {
    __shared__ float s_p[64*100];
    int b = blockIdx.x, t = threadIdx.x;
    for (int i = t; i < 6400; i += 256) s_p[i] = g_pool[(size_t)b*6400 + i];
    __syncthreads();
    int oc = t >> 3, py = t & 7;
    float acc[8];
    float bz = bias[oc];
    #pragma unroll
    for (int px = 0; px < 8; px++) acc[px] = bz;
    for (int ic = 0; ic < 64; ic++) {
        const float* ip = s_p + ic*100 + py*10;
        const float* wp = w + (size_t)oc*576 + ic*9;
        float w0 = wp[0], w1 = wp[1], w2 = wp[2];
        float w3 = wp[3], w4 = wp[4], w5 = wp[5];
        float w6 = wp[6], w7 = wp[7], w8 = wp[8];
        #pragma unroll
        for (int px = 0; px < 8; px++) {
            acc[px] += ip[px]*w0      + ip[px+1]*w1    + ip[px+2]*w2
                     + ip[10+px]*w3   + ip[10+px+1]*w4 + ip[10+px+2]*w5
                     + ip[20+px]*w6   + ip[20+px+1]*w7 + ip[20+px+2]*w8;
        }
    }
    float* dst = g_c2 + (size_t)b*2048 + oc*64 + py*8;
    #pragma unroll
    for (int px = 0; px < 8; px++) dst[px] = fmaxf(acc[px], 0.f);
}

// ==================================================================
// Kernel 9: fc1(2048->128)+ReLU then head(128->12)+tanh
// ==================================================================
__global__ void k_fc(const float* __restrict__ fc1w, const float* __restrict__ fc1b,
                     const float* __restrict__ hw,   const float* __restrict__ hb,
                     float* __restrict__ out) {
    __shared__ float sh[128];
    int b = blockIdx.x, j = threadIdx.x;
    const float* xin = g_c2 + (size_t)b*2048;
    const float* wr  = fc1w + (size_t)j*2048;
    float s = fc1b[j];
    for (int k = 0; k < 2048; k++) s += xin[k]*wr[k];
    sh[j] = fmaxf(s, 0.f);
    __syncthreads();
    if (j < 12) {
        float s2 = hb[j];
        const float* hr = hw + j*128;
        for (int k = 0; k < 128; k++) s2 += sh[k]*hr[k];
        out[b*12 + j] = tanhf(s2);
    }
}

// ==================================================================
extern "C" void kernel_launch(void* const* d_in, const int* in_sizes, int n_in,
                              void* d_out, int out_size) {
    const float* x       = (const float*)d_in[0];
    const float* box     = (const float*)d_in[1];
    const float* stem_w  = (const float*)d_in[2];
    const float* stem_g  = (const float*)d_in[3];
    const float* stem_b  = (const float*)d_in[4];
    const float* conv1_w = (const float*)d_in[5];
    const float* conv1_b = (const float*)d_in[6];
    const float* bn1_g   = (const float*)d_in[7];
    const float* bn1_b   = (const float*)d_in[8];
    const float* conv2_w = (const float*)d_in[9];
    const float* conv2_b = (const float*)d_in[10];
    const float* fc1_w   = (const float*)d_in[11];
    const float* fc1_b   = (const float*)d_in[12];
    const float* head_w  = (const float*)d_in[13];
    const float* head_b  = (const float*)d_in[14];
    float* out = (float*)d_out;

    float *p_stats_b, *p_bn_c1, *p_c1;
    cudaGetSymbolAddress((void**)&p_stats_b, g_stats_b);
    cudaGetSymbolAddress((void**)&p_bn_c1,   g_bn_c1);
    cudaGetSymbolAddress((void**)&p_c1,      g_c1);

    k_stem<<<dim3(8,16,16), dim3(16,8)>>>(x, stem_w);
    k_stem_bn_fin<<<64, 256>>>(stem_g, stem_b);
    k_bnpool3<<<(NB*CF*HF*64)/256, 256>>>();
    k_gsample<<<dim3(128,16,2), dim3(128,2)>>>();
    k_roialign<<<(NROI*64*NPIX + 255)/256, 256>>>(box);
    k_conv1<<<dim3(16,8,4), 128>>>(conv1_w);
    k_c1comb<<<(C1TOT + 255)/256, 256>>>(conv1_b);
    k_stats<<<dim3(16,64), 256>>>(p_c1, p_stats_b, C1N);
    k_stats_fin<<<1,64>>>(p_stats_b, bn1_g, bn1_b, p_bn_c1, 1.0f/7056.0f);
    k_bnpool2<<<(NB*64*100 + 255)/256, 256>>>();
    k_conv2<<<16, 256>>>(conv2_w, conv2_b);
    k_fc<<<16, 128>>>(fc1_w, fc1_b, head_w, head_b, out);
}

// round 8
// speedup vs baseline: 1.1236x; 1.1236x over previous
#include <cuda_runtime.h>
#include <math.h>

typedef unsigned long long ull;

// ---------------- problem constants ----------------
#define NB   16
#define HF   128
#define WF   128
#define CF   64
#define CH   704
#define PP   23
#define NPIX (PP*PP)      // 529
#define NROI 176
#define C1N  441          // 21*21
#define C1TOT (NB*64*C1N)

// ---------------- scratch (device globals) ----------------
__device__ float g_stem[(size_t)NB*64*256*256];     // 268 MB fp32 pre-BN
__device__ float g_f  [(size_t)NB*CF*HF*WF];
__device__ float g_xt1[(size_t)NB*CF*HF*WF];
__device__ float g_xt2[(size_t)NB*CF*HF*WF];
__device__ float g_h  [(size_t)NB*CH*NPIX];
__device__ float g_c1p[(size_t)4*C1TOT];
__device__ float g_c1 [(size_t)C1TOT];
__device__ float g_pool[(size_t)NB*64*10*10];
__device__ float g_c2 [(size_t)NB*32*8*8];
__device__ float g_spart_s[64*2048];
__device__ float g_spart_q[64*2048];
__device__ float g_stats_b[64*16*2];
__device__ float g_bn_stem[64*2];
__device__ float g_bn_c1[64*2];

// ---------------- packed f32x2 helpers ----------------
__device__ __forceinline__ ull pack2(float lo, float hi) {
    ull r; asm("mov.b64 %0, {%1, %2};" : "=l"(r) : "f"(lo), "f"(hi)); return r;
}
__device__ __forceinline__ void unpack2(float& lo, float& hi, ull v) {
    asm("mov.b64 {%0, %1}, %2;" : "=f"(lo), "=f"(hi) : "l"(v));
}
__device__ __forceinline__ void ffma2(ull& acc, ull a, ull b) {
    asm("fma.rn.f32x2 %0, %1, %2, %0;" : "+l"(acc) : "l"(a), "l"(b));
}

// ==================================================================
// Kernel 1: stem conv 7x7 s2 p3, NHWC (16,512,512,3) -> fp32 (16,64,256,256)
// block (32,4): tile 32x (x) * 16 rows; thread: 4 rows x 8 oc (oc packed pairs)
// f32x2 FFMA; fused BN partial stats.  [R4/R6-measured configuration]
// ==================================================================
__global__ __launch_bounds__(128) void k_stem(const float* __restrict__ x,
                                              const float* __restrict__ w) {
    __shared__ float s_in[3*37*72];      // 31968 B
    __shared__ ull   s_w2u[588];         // 1176 floats, oc-pair packed
    __shared__ float s_sum[32], s_sq[32];
    float* s_w2 = (float*)s_w2u;

    const int tx = threadIdx.x, ty = threadIdx.y;
    const int tid = ty*32 + tx;
    const int lane = tid & 31, wid = tid >> 5;
    const int bx = blockIdx.x, by = blockIdx.y, b = blockIdx.z;
    const int blockflat = (b*16 + by)*8 + bx;         // 0..2047
    const int ox  = bx*32 + tx;
    const int iy0 = by*32 - 3;
    const int ix0 = bx*64 - 3;

    // input patch load, c fastest in gmem order for coalescing
    for (int i = tid; i < 3*37*69; i += 128) {
        int py = i / 207;
        int rem = i - py*207;
        int px = rem / 3;
        int c  = rem - px*3;
        int ih = iy0 + py, iw = ix0 + px;
        float v = 0.f;
        if (ih >= 0 && ih < 512 && iw >= 0 && iw < 512)
            v = x[((size_t)(b*512 + ih)*512 + iw)*3 + c];
        s_in[c*2664 + py*72 + px] = v;
    }

    for (int ocb = 0; ocb < 8; ocb++) {
        __syncthreads();   // protects s_w2 reuse + prior round's s_sum reads
        for (int i = tid; i < 1176; i += 128)
            s_w2[i] = w[(ocb*8 + (i & 7))*147 + (i >> 3)];
        __syncthreads();

        ull acc2[4][4];
        #pragma unroll
        for (int r = 0; r < 4; r++)
            #pragma unroll
            for (int op = 0; op < 4; op++) acc2[r][op] = 0ull;

        #pragma unroll
        for (int c = 0; c < 3; c++) {
            #pragma unroll
            for (int ky = 0; ky < 7; ky++) {
                const float* ip = &s_in[c*2664 + (2*ty + ky)*72 + 2*tx];
                const ull*   wp = &s_w2u[(c*49 + ky*7)*4];
                #pragma unroll
                for (int kx = 0; kx < 7; kx++) {
                    ull iv[4];
                    #pragma unroll
                    for (int r = 0; r < 4; r++) {
                        float t = ip[r*576 + kx];
                        iv[r] = pack2(t, t);
                    }
                    #pragma unroll
                    for (int op = 0; op < 4; op++) {
                        ull wv = wp[kx*4 + op];
                        #pragma unroll
                        for (int r = 0; r < 4; r++) ffma2(acc2[r][op], iv[r], wv);
                    }
                }
            }
        }

        // store + fused per-oc stats
        #pragma unroll
        for (int op = 0; op < 4; op++) {
            float v0[4], v1[4];
            #pragma unroll
            for (int r = 0; r < 4; r++) unpack2(v0[r], v1[r], acc2[r][op]);
            #pragma unroll
            for (int half = 0; half < 2; half++) {
                int o = 2*op + half;
                int oc = ocb*8 + o;
                float* outp = g_stem + ((size_t)(b*64 + oc)*256 + by*16 + ty)*256 + ox;
                float s = 0.f, q = 0.f;
                #pragma unroll
                for (int r = 0; r < 4; r++) {
                    float v = half ? v1[r] : v0[r];
                    s += v; q += v*v;
                    outp[r*1024] = v;               // 4 rows * 256
                }
                #pragma unroll
                for (int off = 16; off; off >>= 1) {
                    s += __shfl_xor_sync(0xffffffffu, s, off);
                    q += __shfl_xor_sync(0xffffffffu, q, off);
                }
                if (lane == 0) { s_sum[wid*8 + o] = s; s_sq[wid*8 + o] = q; }
            }
        }
        __syncthreads();
        if (tid < 16) {
            int o = tid >> 1;
            if ((tid & 1) == 0) {
                float S = s_sum[o] + s_sum[8+o] + s_sum[16+o] + s_sum[24+o];
                g_spart_s[(ocb*8 + o)*2048 + blockflat] = S;
            } else {
                float Q = s_sq[o] + s_sq[8+o] + s_sq[16+o] + s_sq[24+o];
                g_spart_q[(ocb*8 + o)*2048 + blockflat] = Q;
            }
        }
    }
}

// ==================================================================
// Kernel 2: combine stem stats -> BN scale/bias (deterministic)
// ==================================================================
__global__ void k_stem_bn_fin(const float* __restrict__ g,
                              const float* __restrict__ bta) {
    __shared__ float ss[256], sq[256];
    int oc = blockIdx.x, t = threadIdx.x;
    float S = 0.f, Q = 0.f;
    #pragma unroll
    for (int j = 0; j < 8; j++) {
        int idx = oc*2048 + t*8 + j;
        S += g_spart_s[idx];
        Q += g_spart_q[idx];
    }
    ss[t] = S; sq[t] = Q;
    __syncthreads();
    for (int st = 128; st > 0; st >>= 1) {
        if (t < st) { ss[t] += ss[t+st]; sq[t] += sq[t+st]; }
        __syncthreads();
    }
    if (t == 0) {
        const float invN = 1.0f/(16.0f*65536.0f);
        float m  = ss[0]*invN;
        float v  = sq[0]*invN - m*m;
        float sc = g[oc] * rsqrtf(v + 1e-5f);
        g_bn_stem[oc*2 + 0] = sc;
        g_bn_stem[oc*2 + 1] = bta[oc] - m*sc;
    }
}

// ==================================================================
// Kernel 3: BN + ReLU + maxpool 3x3 s2 p1, vectorized (2 outputs/thread)
// ==================================================================
__global__ void k_bnpool3() {
    int idx = blockIdx.x*256 + threadIdx.x;
    if (idx >= NB*CF*HF*64) return;
    int xo2 = idx & 63;               // output x-pair (2*xo2, 2*xo2+1)
    int yo  = (idx >> 6) & 127;
    int cb  = idx >> 13;              // b*64 + c
    int c   = cb & 63;
    float sc = g_bn_stem[c*2], bi = g_bn_stem[c*2 + 1];
    const float* p = g_stem + (size_t)cb*65536;
    float m0 = -3.402823466e+38f, m1 = m0;
    #pragma unroll
    for (int ky = 0; ky < 3; ky++) {
        int iy = 2*yo - 1 + ky;
        if (iy < 0 || iy > 255) continue;
        const float* row = p + iy*256;
        float4 qv = *reinterpret_cast<const float4*>(row + 4*xo2);
        float a0 = sc*qv.x + bi, a1 = sc*qv.y + bi;
        float a2 = sc*qv.z + bi, a3 = sc*qv.w + bi;
        if (xo2 > 0) {
            float lf = sc*row[4*xo2 - 1] + bi;
            m0 = fmaxf(m0, lf);
        }
        m0 = fmaxf(m0, fmaxf(a0, a1));
        m1 = fmaxf(m1, fmaxf(a1, fmaxf(a2, a3)));
    }
    float2 outv;
    outv.x = fmaxf(m0, 0.f);
    outv.y = fmaxf(m1, 0.f);
    *reinterpret_cast<float2*>(g_f + (size_t)cb*16384 + yo*128 + 2*xo2) = outv;
}

// ==================================================================
// Kernel 4: grid_sample +/-5 deg, geometry hoisted; block (128,2)
// [R5/R6-measured configuration, ~60us]
// ==================================================================
__global__ __launch_bounds__(256) void k_gsample() {
    const int xo = threadIdx.x, yo = blockIdx.x;
    const int b = blockIdx.y, which = blockIdx.z;
    const int chalf = threadIdx.y;
    const float C5 = 0.99619469809174553f;
    const float S5 = 0.08715574274765817f;
    float gx = (float)(2*xo + 1) * (1.0f/128.0f) - 1.0f;
    float gy = (float)(2*yo + 1) * (1.0f/128.0f) - 1.0f;
    float g0, g1;
    if (which == 0) { g0 =  C5*gx + S5*gy; g1 = -S5*gx + C5*gy; }
    else            { g0 =  C5*gx - S5*gy; g1 =  S5*gx + C5*gy; }
    float ixf = ((g0 + 1.f)*128.f - 1.f)*0.5f;
    float iyf = ((g1 + 1.f)*128.f - 1.f)*0.5f;
    float x0f = floorf(ixf), y0f = floorf(iyf);
    int x0i = (int)x0f, y0i = (int)y0f;
    float lx = ixf - x0f, ly = iyf - y0f;
    float hx = 1.f - lx,  hy = 1.f - ly;
    bool vx0 = (x0i >= 0) && (x0i < 128);
    bool vx1 = (x0i + 1 >= 0) && (x0i + 1 < 128);
    bool vy0 = (y0i >= 0) && (y0i < 128);
    bool vy1 = (y0i + 1 >= 0) && (y0i + 1 < 128);
    int cx0 = min(max(x0i, 0), 127), cx1 = min(max(x0i + 1, 0), 127);
    int cy0 = min(max(y0i, 0), 127), cy1 = min(max(y0i + 1, 0), 127);
    int o00 = cy0*128 + cx0, o01 = cy0*128 + cx1;
    int o10 = cy1*128 + cx0, o11 = cy1*128 + cx1;
    float w00 = (vx0 && vy0) ? hx*hy : 0.f;
    float w01 = (vx1 && vy0) ? lx*hy : 0.f;
    float w10 = (vx0 && vy1) ? hx*ly : 0.f;
    float w11 = (vx1 && vy1) ? lx*ly : 0.f;

    const float* base = g_f + ((size_t)b*64 + chalf*32)*16384;
    float* dst = (which ? g_xt2 : g_xt1)
               + ((size_t)b*64 + chalf*32)*16384 + yo*128 + xo;
    #pragma unroll 8
    for (int c = 0; c < 32; c++) {
        const float* pl = base + c*16384;
        float v = __ldg(pl + o00)*w00 + __ldg(pl + o01)*w01
                + __ldg(pl + o10)*w10 + __ldg(pl + o11)*w11;
        dst[c*16384] = v;
    }
}

// ==================================================================
// Kernel 5: ROI align (176 rois) -> concat buffer g_h
// thread = (roi, pixel, c-quarter); geometry computed once per 16 channels
// ==================================================================
__global__ __launch_bounds__(256) void k_roialign(const float* __restrict__ box) {
    int idx = blockIdx.x*256 + threadIdx.x;
    if (idx >= NROI*4*NPIX) return;
    int p  = idx % NPIX;
    int t2 = idx / NPIX;
    int cq = t2 & 3;
    int r  = t2 >> 2;

    const float* src; int bb, k, och0;
    if (r < 112) { k = r >> 4; bb = r & 15; src = g_f; och0 = k*64; }
    else {
        int u = r - 112; int grp = u >> 4; bb = u & 15; k = grp & 1;
        src = (grp < 2) ? g_xt1 : g_xt2;
        och0 = 448 + grp*64;
    }
    const float* bp = box + bb*28 + k*4;
    float x1 = bp[0]*0.25f, y1v = bp[1]*0.25f, x2 = bp[2]*0.25f, y2 = bp[3]*0.25f;
    float bw = fmaxf(x2 - x1, 1.0f) * (1.0f/23.0f);
    float bh = fmaxf(y2 - y1v, 1.0f) * (1.0f/23.0f);
    int py = p / 23, px = p - py*23;

    // precompute 4 sample points x 4 taps (offsets + empty-folded weights)
    int   off[4][4];
    float wt [4][4];
    int sp = 0;
    #pragma unroll
    for (int dy = 0; dy < 2; dy++) {
        float posy = (float)py + 0.25f + 0.5f*(float)dy;
        float yv = y1v + posy*bh;
        bool ey = (yv < -1.0f) || (yv > 128.0f);
        float yc  = fminf(fmaxf(yv, 0.f), 127.f);
        float y0f = floorf(yc);
        int y0 = (int)y0f; int y1i = min(y0 + 1, 127);
        float ly = yc - y0f, hy = 1.f - ly;
        #pragma unroll
        for (int dx = 0; dx < 2; dx++) {
            float posx = (float)px + 0.25f + 0.5f*(float)dx;
            float xv = x1 + posx*bw;
            bool ex = (xv < -1.0f) || (xv > 128.0f);
            float xc  = fminf(fmaxf(xv, 0.f), 127.f);
            float x0f = floorf(xc);
            int x0 = (int)x0f; int x1i = min(x0 + 1, 127);
            float lx = xc - x0f, hx = 1.f - lx;
            float m = (ey || ex) ? 0.f : 1.f;
            off[sp][0] = y0*128  + x0;  wt[sp][0] = hy*hx*m;
            off[sp][1] = y0*128  + x1i; wt[sp][1] = hy*lx*m;
            off[sp][2] = y1i*128 + x0;  wt[sp][2] = ly*hx*m;
            off[sp][3] = y1i*128 + x1i; wt[sp][3] = ly*lx*m;
            sp++;
        }
    }

    const float* plane0 = src + ((size_t)bb*64 + cq*16)*16384;
    float* dst = g_h + ((size_t)bb*CH + och0 + cq*16)*NPIX + p;
    #pragma unroll 2
    for (int c = 0; c < 16; c++) {
        const float* pl = plane0 + c*16384;
        float acc = 0.f;
        #pragma unroll
        for (int s2 = 0; s2 < 4; s2++) {
            float v = __ldg(pl + off[s2][0])*wt[s2][0]
                    + __ldg(pl + off[s2][1])*wt[s2][1]
                    + __ldg(pl + off[s2][2])*wt[s2][2]
                    + __ldg(pl + off[s2][3])*wt[s2][3];
            acc += v;
        }
        dst[c*NPIX] = acc * 0.25f;
    }
}

// ==================================================================
// Kernel 6: conv1 704->64 3x3 valid, K-split x4, f32x2 FFMA, oc pairs
// ==================================================================
__global__ __launch_bounds__(128) void k_conv1(const float* __restrict__ w) {
    __shared__ float s_in[16*529];
    __shared__ ull   s_w2u[576];
    float* s_w2 = (float*)s_w2u;
    const int b = blockIdx.x, ocb = blockIdx.y, ks = blockIdx.z;
    const int tid = threadIdx.x;

    int py[4], px[4]; bool val[4];
    #pragma unroll
    for (int j = 0; j < 4; j++) {
        int p = tid + 128*j;
        val[j] = (p < C1N);
        int pc = val[j] ? p : 0;
        py[j] = pc / 21; px[j] = pc - py[j]*21;
    }

    ull acc2[4][4];
    #pragma unroll
    for (int j = 0; j < 4; j++)
        #pragma unroll
        for (int op = 0; op < 4; op++) acc2[j][op] = 0ull;

    for (int icb = ks*11; icb < ks*11 + 11; icb++) {
        __syncthreads();
        for (int i = tid; i < 16*529; i += 128) {
            int ci = i / 529, pp = i - ci*529;
            s_in[i] = g_h[((size_t)b*CH + icb*16 + ci)*NPIX + pp];
        }
        for (int i = tid; i < 1152; i += 128)
            s_w2[i] = w[(size_t)(ocb*8 + (i & 7))*6336 + icb*144 + (i >> 3)];
        __syncthreads();

        for (int ci = 0; ci < 16; ci++) {
            const float* ip = s_in + ci*529;
            const ull*   wp = &s_w2u[ci*9*4];
            #pragma unroll
            for (int ky = 0; ky < 3; ky++) {
                #pragma unroll
                for (int kx = 0; kx < 3; kx++) {
                    ull iv[4];
                    #pragma unroll
                    for (int j = 0; j < 4; j++) {
                        float t = ip[(py[j] + ky)*23 + px[j] + kx];
                        iv[j] = pack2(t, t);
                    }
                    #pragma unroll
                    for (int op = 0; op < 4; op++) {
                        ull wv = wp[(ky*3 + kx)*4 + op];
                        #pragma unroll
                        for (int j = 0; j < 4; j++) ffma2(acc2[j][op], iv[j], wv);
                    }
                }
            }
        }
    }
    #pragma unroll
    for (int op = 0; op < 4; op++) {
        #pragma unroll
        for (int j = 0; j < 4; j++) {
            float lo, hi; unpack2(lo, hi, acc2[j][op]);
            if (val[j]) {
                int oc0 = ocb*8 + 2*op;
                float* dst = g_c1p + (size_t)ks*C1TOT + ((size_t)b*64)*C1N + tid + 128*j;
                dst[(size_t)oc0*C1N]       = lo;
                dst[(size_t)(oc0 + 1)*C1N] = hi;
            }
        }
    }
}

__global__ void k_c1comb(const float* __restrict__ bias) {
    int idx = blockIdx.x*256 + threadIdx.x;
    if (idx >= C1TOT) return;
    int oc = (idx / C1N) & 63;
    float v = g_c1p[idx] + g_c1p[C1TOT + idx] + g_c1p[2*C1TOT + idx]
            + g_c1p[3*C1TOT + idx] + bias[oc];
    g_c1[idx] = v;
}

// ==================================================================
// conv1 BN stats
// ==================================================================
__global__ void k_stats(const float* __restrict__ src, float* __restrict__ partial,
                        int planeN) {
    int b = blockIdx.x, oc = blockIdx.y;
    const float* p = src + ((size_t)b*64 + oc)*(size_t)planeN;
    float s = 0.f, q = 0.f;
    for (int i = threadIdx.x; i < planeN; i += blockDim.x) {
        float v = p[i]; s += v; q += v*v;
    }
    __shared__ float ss[256], sq[256];
    ss[threadIdx.x] = s; sq[threadIdx.x] = q;
    __syncthreads();
    for (int st = 128; st > 0; st >>= 1) {
        if (threadIdx.x < st) {
            ss[threadIdx.x] += ss[threadIdx.x + st];
            sq[threadIdx.x] += sq[threadIdx.x + st];
        }
        __syncthreads();
    }
    if (threadIdx.x == 0) {
        partial[(oc*16 + b)*2 + 0] = ss[0];
        partial[(oc*16 + b)*2 + 1] = sq[0];
    }
}

__global__ void k_stats_fin(const float* __restrict__ partial,
                            const float* __restrict__ g, const float* __restrict__ bta,
                            float* __restrict__ bn, float invN) {
    int oc = threadIdx.x;
    float s = 0.f, q = 0.f;
    for (int b = 0; b < 16; b++) {
        s += partial[(oc*16 + b)*2 + 0];
        q += partial[(oc*16 + b)*2 + 1];
    }
    float m  = s*invN;
    float v  = q*invN - m*m;
    float sc = g[oc] * rsqrtf(v + 1e-5f);
    bn[oc*2 + 0] = sc;
    bn[oc*2 + 1] = bta[oc] - m*sc;
}

// ==================================================================
// Kernel 7: BN + ReLU + maxpool 2x2 s2
// ==================================================================
__global__ void k_bnpool2() {
    int idx = blockIdx.x*256 + threadIdx.x;
    if (idx >= NB*64*100) return;
    int xo = idx % 10;
    int yo = (idx / 10) % 10;
    int cb = idx / 100;
    int c  = cb & 63;
    float sc = g_bn_c1[c*2], bi = g_bn_c1[c*2 + 1];
    const float* p = g_c1 + (size_t)cb*C1N;
    float m = -3.402823466e+38f;
    #pragma unroll
    for (int dy = 0; dy < 2; dy++)
        #pragma unroll
        for (int dx = 0; dx < 2; dx++) {
            float v = sc*p[(2*yo + dy)*21 + 2*xo + dx] + bi;
            m = fmaxf(m, v);
        }
    g_pool[idx] = fmaxf(m, 0.f);
}

// ==================================================================
// Kernel 8: conv2 64->32 3x3 + ReLU, smem-staged; block per image
// ==================================================================
__global__ __launch_bounds__(256) void k_conv2(const float* __restrict__ w,
                                               const float* __restrict__ bias) {
    __shared__ float s_p[64*100];
    int b = blockIdx.x, t = threadIdx.x;
    for (int i = t; i < 6400; i += 256) s_p[i] = g_pool[(size_t)b*6400 + i];
    __syncthreads();
    int oc = t >> 3, py = t & 7;
    float acc[8];
    float bz = bias[oc];
    #pragma unroll
    for (int px = 0; px < 8; px++) acc[px] = bz;
    for (int ic = 0; ic < 64; ic++) {
        const float* ip = s_p + ic*100 + py*10;
        const float* wp = w + (size_t)oc*576 + ic*9;
        float w0 = wp[0], w1 = wp[1], w2 = wp[2];
        float w3 = wp[3], w4 = wp[4], w5 = wp[5];
        float w6 = wp[6], w7 = wp[7], w8 = wp[8];
        #pragma unroll
        for (int px = 0; px < 8; px++) {
            acc[px] += ip[px]*w0      + ip[px+1]*w1    + ip[px+2]*w2
                     + ip[10+px]*w3   + ip[10+px+1]*w4 + ip[10+px+2]*w5
                     + ip[20+px]*w6   + ip[20+px+1]*w7 + ip[20+px+2]*w8;
        }
    }
    float* dst = g_c2 + (size_t)b*2048 + oc*64 + py*8;
    #pragma unroll
    for (int px = 0; px < 8; px++) dst[px] = fmaxf(acc[px], 0.f);
}

// ==================================================================
// Kernel 9: fc1(2048->128)+ReLU then head(128->12)+tanh
// ==================================================================
__global__ void k_fc(const float* __restrict__ fc1w, const float* __restrict__ fc1b,
                     const float* __restrict__ hw,   const float* __restrict__ hb,
                     float* __restrict__ out) {
    __shared__ float sh[128];
    int b = blockIdx.x, j = threadIdx.x;
    const float* xin = g_c2 + (size_t)b*2048;
    const float* wr  = fc1w + (size_t)j*2048;
    float s = fc1b[j];
    for (int k = 0; k < 2048; k++) s += xin[k]*wr[k];
    sh[j] = fmaxf(s, 0.f);
    __syncthreads();
    if (j < 12) {
        float s2 = hb[j];
        const float* hr = hw + j*128;
        for (int k = 0; k < 128; k++) s2 += sh[k]*hr[k];
        out[b*12 + j] = tanhf(s2);
    }
}

// ==================================================================
extern "C" void kernel_launch(void* const* d_in, const int* in_sizes, int n_in,
                              void* d_out, int out_size) {
    const float* x       = (const float*)d_in[0];
    const float* box     = (const float*)d_in[1];
    const float* stem_w  = (const float*)d_in[2];
    const float* stem_g  = (const float*)d_in[3];
    const float* stem_b  = (const float*)d_in[4];
    const float* conv1_w = (const float*)d_in[5];
    const float* conv1_b = (const float*)d_in[6];
    const float* bn1_g   = (const float*)d_in[7];
    const float* bn1_b   = (const float*)d_in[8];
    const float* conv2_w = (const float*)d_in[9];
    const float* conv2_b = (const float*)d_in[10];
    const float* fc1_w   = (const float*)d_in[11];
    const float* fc1_b   = (const float*)d_in[12];
    const float* head_w  = (const float*)d_in[13];
    const float* head_b  = (const float*)d_in[14];
    float* out = (float*)d_out;

    float *p_stats_b, *p_bn_c1, *p_c1;
    cudaGetSymbolAddress((void**)&p_stats_b, g_stats_b);
    cudaGetSymbolAddress((void**)&p_bn_c1,   g_bn_c1);
    cudaGetSymbolAddress((void**)&p_c1,      g_c1);

    k_stem<<<dim3(8,16,16), dim3(32,4)>>>(x, stem_w);
    k_stem_bn_fin<<<64, 256>>>(stem_g, stem_b);
    k_bnpool3<<<(NB*CF*HF*64)/256, 256>>>();
    k_gsample<<<dim3(128,16,2), dim3(128,2)>>>();
    k_roialign<<<(NROI*4*NPIX + 255)/256, 256>>>(box);
    k_conv1<<<dim3(16,8,4), 128>>>(conv1_w);
    k_c1comb<<<(C1TOT + 255)/256, 256>>>(conv1_b);
    k_stats<<<dim3(16,64), 256>>>(p_c1, p_stats_b, C1N);
    k_stats_fin<<<1,64>>>(p_stats_b, bn1_g, bn1_b, p_bn_c1, 1.0f/7056.0f);
    k_bnpool2<<<(NB*64*100 + 255)/256, 256>>>();
    k_conv2<<<16, 256>>>(conv2_w, conv2_b);
    k_fc<<<16, 128>>>(fc1_w, fc1_b, head_w, head_b, out);
}